// round 1
// baseline (speedup 1.0000x reference)
#include <cuda_runtime.h>
#include <cuda_bf16.h>

#define DIM    384
#define HEADS  12
#define TOK    49
#define HD     32
#define NTOK   3136
#define BATCH  32
#define M_TOTAL (BATCH * NTOK)   // 100352 rows
#define QKV_N  (3 * DIM)         // 1152
#define NWIN   (M_TOTAL / TOK)   // 2048 windows total

// Scratch (static device globals — allocation-free per harness rules)
__device__ float g_qkv[(size_t)M_TOTAL * QKV_N];   // [100352, 1152]
__device__ float g_att[(size_t)M_TOTAL * DIM];     // [100352, 384]
__device__ float g_bias[HEADS * TOK * TOK];        // [12, 49, 49]

// ---------------------------------------------------------------------------
// Kernel 1: gather relative-position bias into [H, 49, 49]
// ---------------------------------------------------------------------------
__global__ void bias_kernel(const float* __restrict__ table,
                            const int* __restrict__ ridx) {
    int i = blockIdx.x * blockDim.x + threadIdx.x;   // over TOK*TOK*HEADS
    if (i < TOK * TOK * HEADS) {
        int h = i % HEADS;
        int p = i / HEADS;                           // p in [0, 2401)
        g_bias[h * TOK * TOK + p] = table[ridx[p] * HEADS + h];
    }
}

// ---------------------------------------------------------------------------
// Kernel 2/4: fp32 SGEMM C = A[M,K] @ B[K,N] + bias[N]
// 128x128 block tile, BK=8, 256 threads, 8x8 per-thread microtile.
// Requires M%128==0, N%128==0, K%8==0 (holds: 100352, 1152/384, 384).
// ---------------------------------------------------------------------------
__global__ __launch_bounds__(256)
void sgemm_bias(const float* __restrict__ A, const float* __restrict__ Bm,
                const float* __restrict__ bias, float* __restrict__ C,
                int M, int N, int K) {
    const int BM = 128, BN = 128, BK = 8;
    __shared__ float As[BK][BM];
    __shared__ float Bs[BK][BN];

    int tid = threadIdx.x;
    int bm = blockIdx.y * BM;
    int bn = blockIdx.x * BN;
    int tx = tid % 16;           // column group
    int ty = tid / 16;           // row group

    float acc[8][8];
    #pragma unroll
    for (int i = 0; i < 8; i++)
        #pragma unroll
        for (int j = 0; j < 8; j++) acc[i][j] = 0.f;

    // load index mapping
    int arow = tid >> 1;          // 0..127
    int acol = (tid & 1) * 4;     // 0 or 4
    int brow = tid >> 5;          // 0..7
    int bcol = (tid & 31) * 4;    // 0..124

    const float* Aptr = A + (size_t)(bm + arow) * K + acol;
    for (int k0 = 0; k0 < K; k0 += BK) {
        float4 av = *(const float4*)(Aptr + k0);
        float4 bv = *(const float4*)(Bm + (size_t)(k0 + brow) * N + bn + bcol);
        As[acol + 0][arow] = av.x;
        As[acol + 1][arow] = av.y;
        As[acol + 2][arow] = av.z;
        As[acol + 3][arow] = av.w;
        *(float4*)&Bs[brow][bcol] = bv;
        __syncthreads();

        #pragma unroll
        for (int k = 0; k < BK; k++) {
            float ar[8], br[8];
            *(float4*)&ar[0] = *(const float4*)&As[k][ty * 8];
            *(float4*)&ar[4] = *(const float4*)&As[k][ty * 8 + 4];
            *(float4*)&br[0] = *(const float4*)&Bs[k][tx * 8];
            *(float4*)&br[4] = *(const float4*)&Bs[k][tx * 8 + 4];
            #pragma unroll
            for (int i = 0; i < 8; i++)
                #pragma unroll
                for (int j = 0; j < 8; j++)
                    acc[i][j] = fmaf(ar[i], br[j], acc[i][j]);
        }
        __syncthreads();
    }

    #pragma unroll
    for (int i = 0; i < 8; i++) {
        size_t row = (size_t)(bm + ty * 8 + i);
        #pragma unroll
        for (int j = 0; j < 8; j += 4) {
            int col = bn + tx * 8 + j;
            float4 o;
            o.x = acc[i][j + 0] + bias[col + 0];
            o.y = acc[i][j + 1] + bias[col + 1];
            o.z = acc[i][j + 2] + bias[col + 2];
            o.w = acc[i][j + 3] + bias[col + 3];
            *(float4*)&C[row * N + col] = o;
        }
    }
}

// ---------------------------------------------------------------------------
// Kernel 3: windowed attention. One block per (window, head).
// q,k,v: [49,32] fp32 in smem; scores 49x49 + softmax + AV.
// Reads g_qkv, writes g_att in [B,N,C] layout (already (0,2,1,3)-transposed).
// ---------------------------------------------------------------------------
__global__ __launch_bounds__(256)
void attn_kernel(float* __restrict__ out) {
    int w = blockIdx.x;       // 0..NWIN-1
    int h = blockIdx.y;       // 0..HEADS-1
    __shared__ float q[TOK][HD];
    __shared__ float k[TOK][HD + 1];   // pad: avoid 32-way conflict on k[j][dd]
    __shared__ float v[TOK][HD];
    __shared__ float s[TOK][TOK + 1];

    int tid = threadIdx.x;
    const float scale = 0.17677669529663687f;  // 32^-0.5

    size_t base = (size_t)w * TOK * QKV_N + (size_t)h * HD;
    for (int i = tid; i < TOK * HD; i += 256) {
        int t = i / HD, dd = i % HD;
        const float* row = g_qkv + base + (size_t)t * QKV_N + dd;
        q[t][dd] = row[0] * scale;
        k[t][dd] = row[DIM];
        v[t][dd] = row[2 * DIM];
    }
    __syncthreads();

    const float* bptr = g_bias + h * TOK * TOK;
    for (int p = tid; p < TOK * TOK; p += 256) {
        int i = p / TOK, j = p % TOK;
        float acc = bptr[p];
        #pragma unroll
        for (int dd = 0; dd < HD; dd++) acc = fmaf(q[i][dd], k[j][dd], acc);
        s[i][j] = acc;
    }
    __syncthreads();

    if (tid < TOK) {
        float mx = -1e30f;
        #pragma unroll 7
        for (int j = 0; j < TOK; j++) mx = fmaxf(mx, s[tid][j]);
        float sum = 0.f;
        #pragma unroll 7
        for (int j = 0; j < TOK; j++) {
            float e = __expf(s[tid][j] - mx);
            s[tid][j] = e;
            sum += e;
        }
        float inv = 1.0f / sum;
        #pragma unroll 7
        for (int j = 0; j < TOK; j++) s[tid][j] *= inv;
    }
    __syncthreads();

    for (int p = tid; p < TOK * HD; p += 256) {
        int i = p / HD, dd = p % HD;
        float acc = 0.f;
        #pragma unroll
        for (int j = 0; j < TOK; j++) acc = fmaf(s[i][j], v[j][dd], acc);
        out[((size_t)w * TOK + i) * DIM + h * HD + dd] = acc;
    }
}

// ---------------------------------------------------------------------------
extern "C" void kernel_launch(void* const* d_in, const int* in_sizes, int n_in,
                              void* d_out, int out_size) {
    const float* x       = (const float*)d_in[0];
    const float* qkv_w   = (const float*)d_in[1];
    const float* qkv_b   = (const float*)d_in[2];
    const float* proj_w  = (const float*)d_in[3];
    const float* proj_b  = (const float*)d_in[4];
    const float* table   = (const float*)d_in[5];
    const int*   ridx    = (const int*)d_in[6];
    float*       out     = (float*)d_out;

    float *qkv_buf = nullptr, *att_buf = nullptr;
    cudaGetSymbolAddress((void**)&qkv_buf, g_qkv);
    cudaGetSymbolAddress((void**)&att_buf, g_att);

    // 1. bias gather
    {
        int total = TOK * TOK * HEADS;
        bias_kernel<<<(total + 255) / 256, 256>>>(table, ridx);
    }
    // 2. QKV GEMM: [100352,384] @ [384,1152] + qkv_b
    {
        dim3 grid(QKV_N / 128, M_TOTAL / 128);   // (9, 784)
        sgemm_bias<<<grid, 256>>>(x, qkv_w, qkv_b, qkv_buf, M_TOTAL, QKV_N, DIM);
    }
    // 3. window attention
    {
        dim3 grid(NWIN, HEADS);                  // (2048, 12)
        attn_kernel<<<grid, 256>>>(att_buf);
    }
    // 4. proj GEMM: [100352,384] @ [384,384] + proj_b -> d_out
    {
        dim3 grid(DIM / 128, M_TOTAL / 128);     // (3, 784)
        sgemm_bias<<<grid, 256>>>(att_buf, proj_w, proj_b, out, M_TOTAL, DIM, DIM);
    }
}

// round 3
// speedup vs baseline: 1.1462x; 1.1462x over previous
#include <cuda_runtime.h>
#include <cuda_bf16.h>
#include <cstdint>

#define DIM    384
#define HEADS  12
#define TOK    49
#define HD     32
#define NTOK   3136
#define BATCH  32
#define M_TOTAL (BATCH * NTOK)   // 100352 rows
#define QKV_N  (3 * DIM)         // 1152
#define NWIN   (M_TOTAL / TOK)   // 2048 windows total

// Scratch (static device globals — allocation-free per harness rules)
__device__ float g_qkv[(size_t)M_TOTAL * QKV_N];   // [100352, 1152]
__device__ float g_att[(size_t)M_TOTAL * DIM];     // [100352, 384]
__device__ float g_bias[HEADS * TOK * TOK];        // [12, 49, 49]

// ---------------------------------------------------------------------------
// Kernel 1: gather relative-position bias into [H, 49, 49]
// ---------------------------------------------------------------------------
__global__ void bias_kernel(const float* __restrict__ table,
                            const int* __restrict__ ridx) {
    int i = blockIdx.x * blockDim.x + threadIdx.x;
    if (i < TOK * TOK * HEADS) {
        int h = i % HEADS;
        int p = i / HEADS;
        g_bias[h * TOK * TOK + p] = table[ridx[p] * HEADS + h];
    }
}

// ---------------------------------------------------------------------------
// tf32 conversion helper
// ---------------------------------------------------------------------------
__device__ __forceinline__ unsigned int f2tf(float f) {
    unsigned int r;
    asm("cvt.rna.tf32.f32 %0, %1;" : "=r"(r) : "f"(f));
    return r;
}

// ---------------------------------------------------------------------------
// Kernel 2/4: tf32 tensor-core GEMM  C = A[M,K] @ B[K,N] + bias[N]
// 128x128 CTA tile, BK=16, 256 threads (8 warps), warp tile 64x32,
// mma.sync.m16n8k8.tf32, fp32 accumulate. Register double-buffered loads.
// Requires M%128==0, N%128==0, K%16==0.
// ---------------------------------------------------------------------------
__global__ __launch_bounds__(256)
void gemm_tf32(const float* __restrict__ A, const float* __restrict__ B,
               const float* __restrict__ bias, float* __restrict__ C,
               int M, int N, int K) {
    const int BM = 128, BN = 128, BK = 16;
    __shared__ unsigned int As[BK][BM + 8];   // [k][m], +8 pad
    __shared__ unsigned int Bs[BK][BN + 8];   // [k][n]

    int tid  = threadIdx.x;
    int lane = tid & 31;
    int warp = tid >> 5;
    int wm = (warp >> 2) * 64;   // warp row offset within CTA tile (0 or 64)
    int wn = (warp & 3) * 32;    // warp col offset (0,32,64,96)
    int g = lane >> 2;           // groupID   (0..7)
    int t = lane & 3;            // threadID_in_group (0..3)

    int bm = blockIdx.y * BM;
    int bn = blockIdx.x * BN;

    float acc[4][4][4];
    #pragma unroll
    for (int i = 0; i < 4; i++)
        #pragma unroll
        for (int j = 0; j < 4; j++)
            #pragma unroll
            for (int r = 0; r < 4; r++) acc[i][j][r] = 0.f;

    // global load mapping
    int arow = tid >> 2;        // 0..63 (A rows; +64 for second half)
    int aq   = (tid & 3) * 4;   // A col within BK: 0,4,8,12
    int brow = tid >> 4;        // 0..15 (B rows = k)
    int bq   = (tid & 15) * 4;  // B col: 0..60 (first half), +64 second

    const float* Ap0 = A + (size_t)(bm + arow) * K + aq;
    const float* Ap1 = A + (size_t)(bm + arow + 64) * K + aq;
    const float* Bp  = B + (size_t)brow * N + bn;

    // prefetch k0 = 0
    float4 a0v = *(const float4*)(Ap0);
    float4 a1v = *(const float4*)(Ap1);
    float4 b0v = *(const float4*)(Bp + bq);
    float4 b1v = *(const float4*)(Bp + bq + 64);

    int k0 = 0;
    for (;;) {
        // store current prefetch to smem (A transposed, cvt to tf32)
        As[aq + 0][arow]      = f2tf(a0v.x);
        As[aq + 1][arow]      = f2tf(a0v.y);
        As[aq + 2][arow]      = f2tf(a0v.z);
        As[aq + 3][arow]      = f2tf(a0v.w);
        As[aq + 0][arow + 64] = f2tf(a1v.x);
        As[aq + 1][arow + 64] = f2tf(a1v.y);
        As[aq + 2][arow + 64] = f2tf(a1v.z);
        As[aq + 3][arow + 64] = f2tf(a1v.w);
        {
            uint4 u0 = make_uint4(f2tf(b0v.x), f2tf(b0v.y), f2tf(b0v.z), f2tf(b0v.w));
            uint4 u1 = make_uint4(f2tf(b1v.x), f2tf(b1v.y), f2tf(b1v.z), f2tf(b1v.w));
            *(uint4*)&Bs[brow][bq]      = u0;
            *(uint4*)&Bs[brow][bq + 64] = u1;
        }
        __syncthreads();

        k0 += BK;
        bool more = (k0 < K);
        if (more) {
            a0v = *(const float4*)(Ap0 + k0);
            a1v = *(const float4*)(Ap1 + k0);
            const float* bnow = B + (size_t)(k0 + brow) * N + bn;
            b0v = *(const float4*)(bnow + bq);
            b1v = *(const float4*)(bnow + bq + 64);
        }

        // compute on current smem tile: 2 k-steps of 8
        #pragma unroll
        for (int ks = 0; ks < 2; ks++) {
            int kb = ks * 8;
            unsigned int af[4][4];  // [mt][reg]
            unsigned int bf[4][2];  // [nt][reg]
            #pragma unroll
            for (int mt = 0; mt < 4; mt++) {
                int m0 = wm + mt * 16;
                af[mt][0] = As[kb + t][m0 + g];
                af[mt][1] = As[kb + t][m0 + g + 8];
                af[mt][2] = As[kb + t + 4][m0 + g];
                af[mt][3] = As[kb + t + 4][m0 + g + 8];
            }
            #pragma unroll
            for (int nt = 0; nt < 4; nt++) {
                int n0 = wn + nt * 8;
                bf[nt][0] = Bs[kb + t][n0 + g];
                bf[nt][1] = Bs[kb + t + 4][n0 + g];
            }
            #pragma unroll
            for (int mt = 0; mt < 4; mt++)
                #pragma unroll
                for (int nt = 0; nt < 4; nt++) {
                    asm volatile(
                        "mma.sync.aligned.m16n8k8.row.col.f32.tf32.tf32.f32 "
                        "{%0,%1,%2,%3}, {%4,%5,%6,%7}, {%8,%9}, {%0,%1,%2,%3};"
                        : "+f"(acc[mt][nt][0]), "+f"(acc[mt][nt][1]),
                          "+f"(acc[mt][nt][2]), "+f"(acc[mt][nt][3])
                        : "r"(af[mt][0]), "r"(af[mt][1]),
                          "r"(af[mt][2]), "r"(af[mt][3]),
                          "r"(bf[nt][0]), "r"(bf[nt][1]));
                }
        }
        __syncthreads();
        if (!more) break;
    }

    // epilogue: c0:(g,2t) c1:(g,2t+1) c2:(g+8,2t) c3:(g+8,2t+1)
    #pragma unroll
    for (int mt = 0; mt < 4; mt++) {
        int row0 = bm + wm + mt * 16 + g;
        #pragma unroll
        for (int nt = 0; nt < 4; nt++) {
            int col = bn + wn + nt * 8 + 2 * t;
            float bx = bias[col], by = bias[col + 1];
            float2 o0 = make_float2(acc[mt][nt][0] + bx, acc[mt][nt][1] + by);
            float2 o1 = make_float2(acc[mt][nt][2] + bx, acc[mt][nt][3] + by);
            *(float2*)&C[(size_t)row0 * N + col]       = o0;
            *(float2*)&C[(size_t)(row0 + 8) * N + col] = o1;
        }
    }
}

// ---------------------------------------------------------------------------
// Kernel 3: windowed attention. One block per (window, head).
// ---------------------------------------------------------------------------
__global__ __launch_bounds__(256)
void attn_kernel(float* __restrict__ out) {
    int w = blockIdx.x;
    int h = blockIdx.y;
    __shared__ float q[TOK][HD];
    __shared__ float k[TOK][HD + 1];
    __shared__ float v[TOK][HD];
    __shared__ float s[TOK][TOK + 1];

    int tid = threadIdx.x;
    const float scale = 0.17677669529663687f;  // 32^-0.5

    size_t base = (size_t)w * TOK * QKV_N + (size_t)h * HD;
    for (int i = tid; i < TOK * HD; i += 256) {
        int t = i / HD, dd = i % HD;
        const float* row = g_qkv + base + (size_t)t * QKV_N + dd;
        q[t][dd] = row[0] * scale;
        k[t][dd] = row[DIM];
        v[t][dd] = row[2 * DIM];
    }
    __syncthreads();

    const float* bptr = g_bias + h * TOK * TOK;
    for (int p = tid; p < TOK * TOK; p += 256) {
        int i = p / TOK, j = p % TOK;
        float acc = bptr[p];
        #pragma unroll
        for (int dd = 0; dd < HD; dd++) acc = fmaf(q[i][dd], k[j][dd], acc);
        s[i][j] = acc;
    }
    __syncthreads();

    if (tid < TOK) {
        float mx = -1e30f;
        #pragma unroll 7
        for (int j = 0; j < TOK; j++) mx = fmaxf(mx, s[tid][j]);
        float sum = 0.f;
        #pragma unroll 7
        for (int j = 0; j < TOK; j++) {
            float e = __expf(s[tid][j] - mx);
            s[tid][j] = e;
            sum += e;
        }
        float inv = 1.0f / sum;
        #pragma unroll 7
        for (int j = 0; j < TOK; j++) s[tid][j] *= inv;
    }
    __syncthreads();

    for (int p = tid; p < TOK * HD; p += 256) {
        int i = p / HD, dd = p % HD;
        float acc = 0.f;
        #pragma unroll
        for (int j = 0; j < TOK; j++) acc = fmaf(s[i][j], v[j][dd], acc);
        out[((size_t)w * TOK + i) * DIM + h * HD + dd] = acc;
    }
}

// ---------------------------------------------------------------------------
extern "C" void kernel_launch(void* const* d_in, const int* in_sizes, int n_in,
                              void* d_out, int out_size) {
    const float* x       = (const float*)d_in[0];
    const float* qkv_w   = (const float*)d_in[1];
    const float* qkv_b   = (const float*)d_in[2];
    const float* proj_w  = (const float*)d_in[3];
    const float* proj_b  = (const float*)d_in[4];
    const float* table   = (const float*)d_in[5];
    const int*   ridx    = (const int*)d_in[6];
    float*       out     = (float*)d_out;

    float *qkv_buf = nullptr, *att_buf = nullptr;
    cudaGetSymbolAddress((void**)&qkv_buf, g_qkv);
    cudaGetSymbolAddress((void**)&att_buf, g_att);

    // 1. bias gather
    {
        int total = TOK * TOK * HEADS;
        bias_kernel<<<(total + 255) / 256, 256>>>(table, ridx);
    }
    // 2. QKV GEMM: [100352,384] @ [384,1152] + qkv_b
    {
        dim3 grid(QKV_N / 128, M_TOTAL / 128);   // (9, 784)
        gemm_tf32<<<grid, 256>>>(x, qkv_w, qkv_b, qkv_buf, M_TOTAL, QKV_N, DIM);
    }
    // 3. window attention
    {
        dim3 grid(NWIN, HEADS);                  // (2048, 12)
        attn_kernel<<<grid, 256>>>(att_buf);
    }
    // 4. proj GEMM: [100352,384] @ [384,384] + proj_b -> d_out
    {
        dim3 grid(DIM / 128, M_TOTAL / 128);     // (3, 784)
        gemm_tf32<<<grid, 256>>>(att_buf, proj_w, proj_b, out, M_TOTAL, DIM, DIM);
    }
}

// round 4
// speedup vs baseline: 2.2120x; 1.9299x over previous
#include <cuda_runtime.h>
#include <cuda_bf16.h>
#include <cstdint>

#define DIM    384
#define HEADS  12
#define TOK    49
#define HD     32
#define NTOK   3136
#define BATCH  32
#define M_TOTAL (BATCH * NTOK)   // 100352 rows
#define QKV_N  (3 * DIM)         // 1152
#define NWIN   (M_TOTAL / TOK)   // 2048 windows total

// Scratch (static device globals — allocation-free per harness rules)
__device__ float g_qkv[(size_t)M_TOTAL * QKV_N];   // [100352, 1152]
__device__ float g_att[(size_t)M_TOTAL * DIM];     // [100352, 384]
__device__ float g_bias[HEADS * TOK * TOK];        // [12, 49, 49]

// ---------------------------------------------------------------------------
// Kernel 1: gather relative-position bias into [H, 49, 49]
// ---------------------------------------------------------------------------
__global__ void bias_kernel(const float* __restrict__ table,
                            const int* __restrict__ ridx) {
    int i = blockIdx.x * blockDim.x + threadIdx.x;
    if (i < TOK * TOK * HEADS) {
        int h = i % HEADS;
        int p = i / HEADS;
        g_bias[h * TOK * TOK + p] = table[ridx[p] * HEADS + h];
    }
}

// ---------------------------------------------------------------------------
__device__ __forceinline__ unsigned int f2tf(float f) {
    unsigned int r;
    asm("cvt.rna.tf32.f32 %0, %1;" : "=r"(r) : "f"(f));
    return r;
}

// ---------------------------------------------------------------------------
// Kernel 2/4: tf32 tensor-core GEMM, 2-stage smem double buffer.
// C = A[M,K] @ B[K,N] + bias[N]. 128x128 CTA, BK=16, 256 thr, warp 64x32.
// ---------------------------------------------------------------------------
__global__ __launch_bounds__(256)
void gemm_tf32(const float* __restrict__ A, const float* __restrict__ B,
               const float* __restrict__ bias, float* __restrict__ C,
               int M, int N, int K) {
    const int BM = 128, BN = 128, BK = 16;
    __shared__ unsigned int As[2][BK][BM + 8];
    __shared__ unsigned int Bs[2][BK][BN + 8];

    int tid  = threadIdx.x;
    int lane = tid & 31;
    int warp = tid >> 5;
    int wm = (warp >> 2) * 64;
    int wn = (warp & 3) * 32;
    int g = lane >> 2;
    int t = lane & 3;

    int bm = blockIdx.y * BM;
    int bn = blockIdx.x * BN;

    float acc[4][4][4];
    #pragma unroll
    for (int i = 0; i < 4; i++)
        #pragma unroll
        for (int j = 0; j < 4; j++)
            #pragma unroll
            for (int r = 0; r < 4; r++) acc[i][j][r] = 0.f;

    int arow = tid >> 2;
    int aq   = (tid & 3) * 4;
    int brow = tid >> 4;
    int bq   = (tid & 15) * 4;

    const float* Ap0 = A + (size_t)(bm + arow) * K + aq;
    const float* Ap1 = A + (size_t)(bm + arow + 64) * K + aq;

    float4 a0v, a1v, b0v, b1v;

    // ---- load k0=0, store into buffer 0 ----
    a0v = *(const float4*)(Ap0);
    a1v = *(const float4*)(Ap1);
    {
        const float* bp = B + (size_t)brow * N + bn;
        b0v = *(const float4*)(bp + bq);
        b1v = *(const float4*)(bp + bq + 64);
    }
    #define STORE_STAGE(buf)                                                  \
        do {                                                                  \
            As[buf][aq + 0][arow]      = f2tf(a0v.x);                         \
            As[buf][aq + 1][arow]      = f2tf(a0v.y);                         \
            As[buf][aq + 2][arow]      = f2tf(a0v.z);                         \
            As[buf][aq + 3][arow]      = f2tf(a0v.w);                         \
            As[buf][aq + 0][arow + 64] = f2tf(a1v.x);                         \
            As[buf][aq + 1][arow + 64] = f2tf(a1v.y);                         \
            As[buf][aq + 2][arow + 64] = f2tf(a1v.z);                         \
            As[buf][aq + 3][arow + 64] = f2tf(a1v.w);                         \
            uint4 u0 = make_uint4(f2tf(b0v.x), f2tf(b0v.y), f2tf(b0v.z), f2tf(b0v.w)); \
            uint4 u1 = make_uint4(f2tf(b1v.x), f2tf(b1v.y), f2tf(b1v.z), f2tf(b1v.w)); \
            *(uint4*)&Bs[buf][brow][bq]      = u0;                            \
            *(uint4*)&Bs[buf][brow][bq + 64] = u1;                            \
        } while (0)

    #define COMPUTE_STAGE(buf)                                                \
        do {                                                                  \
            _Pragma("unroll")                                                 \
            for (int ks = 0; ks < 2; ks++) {                                  \
                int kb = ks * 8;                                              \
                unsigned int af[4][4];                                        \
                unsigned int bf[4][2];                                        \
                _Pragma("unroll")                                             \
                for (int mt = 0; mt < 4; mt++) {                              \
                    int m0 = wm + mt * 16;                                    \
                    af[mt][0] = As[buf][kb + t][m0 + g];                      \
                    af[mt][1] = As[buf][kb + t][m0 + g + 8];                  \
                    af[mt][2] = As[buf][kb + t + 4][m0 + g];                  \
                    af[mt][3] = As[buf][kb + t + 4][m0 + g + 8];              \
                }                                                             \
                _Pragma("unroll")                                             \
                for (int nt = 0; nt < 4; nt++) {                              \
                    int n0 = wn + nt * 8;                                     \
                    bf[nt][0] = Bs[buf][kb + t][n0 + g];                      \
                    bf[nt][1] = Bs[buf][kb + t + 4][n0 + g];                  \
                }                                                             \
                _Pragma("unroll")                                             \
                for (int mt = 0; mt < 4; mt++)                                \
                    _Pragma("unroll")                                         \
                    for (int nt = 0; nt < 4; nt++) {                          \
                        asm volatile(                                         \
                            "mma.sync.aligned.m16n8k8.row.col.f32.tf32.tf32.f32 " \
                            "{%0,%1,%2,%3}, {%4,%5,%6,%7}, {%8,%9}, {%0,%1,%2,%3};" \
                            : "+f"(acc[mt][nt][0]), "+f"(acc[mt][nt][1]),     \
                              "+f"(acc[mt][nt][2]), "+f"(acc[mt][nt][3])      \
                            : "r"(af[mt][0]), "r"(af[mt][1]),                 \
                              "r"(af[mt][2]), "r"(af[mt][3]),                 \
                              "r"(bf[nt][0]), "r"(bf[nt][1]));                \
                    }                                                         \
            }                                                                 \
        } while (0)

    STORE_STAGE(0);
    __syncthreads();

    int cur = 0;
    for (int k0 = BK; k0 < K; k0 += BK) {
        // issue next-tile global loads
        a0v = *(const float4*)(Ap0 + k0);
        a1v = *(const float4*)(Ap1 + k0);
        const float* bp = B + (size_t)(k0 + brow) * N + bn;
        b0v = *(const float4*)(bp + bq);
        b1v = *(const float4*)(bp + bq + 64);
        // compute current tile while loads are in flight
        COMPUTE_STAGE(cur);
        // stage next tile
        STORE_STAGE(cur ^ 1);
        __syncthreads();
        cur ^= 1;
    }
    COMPUTE_STAGE(cur);

    #pragma unroll
    for (int mt = 0; mt < 4; mt++) {
        int row0 = bm + wm + mt * 16 + g;
        #pragma unroll
        for (int nt = 0; nt < 4; nt++) {
            int col = bn + wn + nt * 8 + 2 * t;
            float bx = bias[col], by = bias[col + 1];
            float2 o0 = make_float2(acc[mt][nt][0] + bx, acc[mt][nt][1] + by);
            float2 o1 = make_float2(acc[mt][nt][2] + bx, acc[mt][nt][3] + by);
            *(float2*)&C[(size_t)row0 * N + col]       = o0;
            *(float2*)&C[(size_t)(row0 + 8) * N + col] = o1;
        }
    }
    #undef STORE_STAGE
    #undef COMPUTE_STAGE
}

// ---------------------------------------------------------------------------
// Kernel 3: windowed attention, register-tiled.
// qT/kT stored transposed [dd][tok] (padded to 52 toks, zeros) so the 4x4
// score tile reads 2 x LDS.128 per dd step. s is [52][52] fp32.
// ---------------------------------------------------------------------------
#define TOKP 52
__global__ __launch_bounds__(256)
void attn_kernel(float* __restrict__ out) {
    int w = blockIdx.x;
    int h = blockIdx.y;
    __shared__ float qT[HD][TOKP];
    __shared__ float kT[HD][TOKP];
    __shared__ float v[TOK][HD];
    __shared__ float s[TOKP][TOKP];

    int tid = threadIdx.x;
    const float scale = 0.17677669529663687f;  // 32^-0.5

    // zero the 3 pad token columns of qT/kT
    for (int i = tid; i < HD * 3; i += 256) {
        int dd = i / 3, tp = TOK + i % 3;
        qT[dd][tp] = 0.f;
        kT[dd][tp] = 0.f;
    }

    size_t base = (size_t)w * TOK * QKV_N + (size_t)h * HD;
    for (int i = tid; i < TOK * (HD / 4); i += 256) {
        int t = i / (HD / 4), dq = (i % (HD / 4)) * 4;
        const float* row = g_qkv + base + (size_t)t * QKV_N + dq;
        float4 qv = *(const float4*)(row);
        float4 kv = *(const float4*)(row + DIM);
        float4 vv = *(const float4*)(row + 2 * DIM);
        qT[dq + 0][t] = qv.x * scale;
        qT[dq + 1][t] = qv.y * scale;
        qT[dq + 2][t] = qv.z * scale;
        qT[dq + 3][t] = qv.w * scale;
        kT[dq + 0][t] = kv.x;
        kT[dq + 1][t] = kv.y;
        kT[dq + 2][t] = kv.z;
        kT[dq + 3][t] = kv.w;
        *(float4*)&v[t][dq] = vv;
    }
    __syncthreads();

    // scores: 13x13 grid of 4x4 tiles, threads 0..168
    const float* bptr = g_bias + h * TOK * TOK;
    if (tid < 169) {
        int i0 = (tid / 13) * 4;
        int j0 = (tid % 13) * 4;
        float acc[4][4];
        #pragma unroll
        for (int r = 0; r < 4; r++)
            #pragma unroll
            for (int c = 0; c < 4; c++) acc[r][c] = 0.f;
        #pragma unroll
        for (int dd = 0; dd < HD; dd++) {
            float4 qa = *(const float4*)&qT[dd][i0];
            float4 ka = *(const float4*)&kT[dd][j0];
            float qr[4] = {qa.x, qa.y, qa.z, qa.w};
            float kc[4] = {ka.x, ka.y, ka.z, ka.w};
            #pragma unroll
            for (int r = 0; r < 4; r++)
                #pragma unroll
                for (int c = 0; c < 4; c++)
                    acc[r][c] = fmaf(qr[r], kc[c], acc[r][c]);
        }
        #pragma unroll
        for (int r = 0; r < 4; r++) {
            int i = i0 + r;
            #pragma unroll
            for (int c = 0; c < 4; c++) {
                int j = j0 + c;
                float b = (i < TOK && j < TOK) ? bptr[i * TOK + j] : 0.f;
                s[i][j] = acc[r][c] + b;
            }
        }
    }
    __syncthreads();

    // softmax per row
    if (tid < TOK) {
        float mx = -1e30f;
        #pragma unroll 7
        for (int j = 0; j < TOK; j++) mx = fmaxf(mx, s[tid][j]);
        float sum = 0.f;
        #pragma unroll 7
        for (int j = 0; j < TOK; j++) {
            float e = __expf(s[tid][j] - mx);
            s[tid][j] = e;
            sum += e;
        }
        float inv = 1.0f / sum;
        #pragma unroll 7
        for (int j = 0; j < TOK; j++) s[tid][j] *= inv;
    }
    __syncthreads();

    // AV: thread per (row, dd-quad): 49*8 = 392 tasks
    for (int p = tid; p < TOK * (HD / 4); p += 256) {
        int i = p / (HD / 4), dq = (p % (HD / 4)) * 4;
        float ox = 0.f, oy = 0.f, oz = 0.f, ow = 0.f;
        #pragma unroll 7
        for (int j = 0; j < TOK; j++) {
            float sv = s[i][j];
            float4 vv = *(const float4*)&v[j][dq];
            ox = fmaf(sv, vv.x, ox);
            oy = fmaf(sv, vv.y, oy);
            oz = fmaf(sv, vv.z, oz);
            ow = fmaf(sv, vv.w, ow);
        }
        float4 o = make_float4(ox, oy, oz, ow);
        *(float4*)&out[((size_t)w * TOK + i) * DIM + h * HD + dq] = o;
    }
}

// ---------------------------------------------------------------------------
extern "C" void kernel_launch(void* const* d_in, const int* in_sizes, int n_in,
                              void* d_out, int out_size) {
    const float* x       = (const float*)d_in[0];
    const float* qkv_w   = (const float*)d_in[1];
    const float* qkv_b   = (const float*)d_in[2];
    const float* proj_w  = (const float*)d_in[3];
    const float* proj_b  = (const float*)d_in[4];
    const float* table   = (const float*)d_in[5];
    const int*   ridx    = (const int*)d_in[6];
    float*       out     = (float*)d_out;

    float *qkv_buf = nullptr, *att_buf = nullptr;
    cudaGetSymbolAddress((void**)&qkv_buf, g_qkv);
    cudaGetSymbolAddress((void**)&att_buf, g_att);

    {
        int total = TOK * TOK * HEADS;
        bias_kernel<<<(total + 255) / 256, 256>>>(table, ridx);
    }
    {
        dim3 grid(QKV_N / 128, M_TOTAL / 128);   // (9, 784)
        gemm_tf32<<<grid, 256>>>(x, qkv_w, qkv_b, qkv_buf, M_TOTAL, QKV_N, DIM);
    }
    {
        dim3 grid(NWIN, HEADS);                  // (2048, 12)
        attn_kernel<<<grid, 256>>>(att_buf);
    }
    {
        dim3 grid(DIM / 128, M_TOTAL / 128);     // (3, 784)
        gemm_tf32<<<grid, 256>>>(att_buf, proj_w, proj_b, out, M_TOTAL, DIM, DIM);
    }
}